// round 16
// baseline (speedup 1.0000x reference)
#include <cuda_runtime.h>
#include <cuda_fp16.h>
#include <cstddef>

#define NN 50000
#define NE 600000
#define DD 128
#define DC 32          // collapsed output width
#define NG 64

#define SCAN_BS 256
#define SCAN_NB ((NN + SCAN_BS - 1) / SCAN_BS)   // 196

#define VB 6250        // vector blocks per vagg (50000 warps)
#define UB SCAN_NB     // scalar-u blocks appended (196)

#define ZB  SCAN_NB                     // zero blocks
#define CB  ((NE + 255) / 256)          // count/fill blocks (2344)
#define MMB 16                          // blocks per 128x32 weight mm
#define GYB ((NN + 127) / 128)          // gemmY blocks (391)
#define PB  ((VB / 16) + 1)             // pool blocks
#define UPB ((NN / 16 + 255) / 256)     // upool blocks (13)

// -------- scratch (device globals; never passed as kernel args from host) --------
__device__ int   g_indeg[NN];
__device__ float g_dinv[NN];
__device__ int   g_rowptr[NN];
__device__ int   g_rank[NE];           // per-edge slot within dst segment
__device__ int   g_scan_tmp[NN];
__device__ int   g_bsum[SCAN_NB];
__device__ __align__(8) int2 g_csr[NE];    // (src, __float_as_int(norm)), node-ordered rows
__device__ float g_u1[NN], g_u2[NN], g_u3[NN];
__device__ __align__(16) float g_M1[DD * DC];
__device__ __align__(16) float g_M2[DD * DC];
__device__ __align__(16) float g_M3[DD * DC];
__device__ __align__(16) float g_Wc[DD * DC];
__device__ float g_cv[4 * DC];
__device__ __align__(16) __half g_Yh0[(size_t)NN * DC];   // fp16 Y ping-pong
__device__ __align__(16) __half g_Yh1[(size_t)NN * DC];
__device__ float g_pool[NG * DC];
__device__ float g_usum[NG * 3];
__device__ unsigned g_poolDone;        // zero-initialized; reset by last block

// pack/unpack helpers
__device__ __forceinline__ uint2 pack_h4(float4 a) {
    __half2 h0 = __floats2half2_rn(a.x, a.y);
    __half2 h1 = __floats2half2_rn(a.z, a.w);
    uint2 r;
    r.x = *reinterpret_cast<unsigned*>(&h0);
    r.y = *reinterpret_cast<unsigned*>(&h1);
    return r;
}
__device__ __forceinline__ void unpack_h8(uint4 r, float4& a, float4& b) {
    __half2 h0 = *reinterpret_cast<__half2*>(&r.x);
    __half2 h1 = *reinterpret_cast<__half2*>(&r.y);
    __half2 h2 = *reinterpret_cast<__half2*>(&r.z);
    __half2 h3 = *reinterpret_cast<__half2*>(&r.w);
    float2 f0 = __half22float2(h0), f1 = __half22float2(h1);
    float2 f2 = __half22float2(h2), f3 = __half22float2(h3);
    a = make_float4(f0.x, f0.y, f1.x, f1.y);
    b = make_float4(f2.x, f2.y, f3.x, f3.y);
}
__device__ __forceinline__ uint4 pack_h8(float4 a, float4 b) {
    uint2 lo = pack_h4(a), hi = pack_h4(b);
    return make_uint4(lo.x, lo.y, hi.x, hi.y);
}

// ======== mm tile with smem-staged B and float4 A reads ========
__device__ __forceinline__ void mm_tile(const float* __restrict__ A,
                                        const float* __restrict__ B,
                                        float* __restrict__ C, int blk) {
    __shared__ float Bs[DD][DC];     // 16 KB
    int t = threadIdx.x;
#pragma unroll
    for (int i = 0; i < 4; i++) {
        int lin = t + i * 256;       // 1024 float4 slots
        int r = lin >> 3, c4 = (lin & 7) << 2;
        *(float4*)&Bs[r][c4] = *(const float4*)(B + r * DC + c4);
    }
    __syncthreads();
    int idx = blk * 256 + t;
    int r = idx >> 5, c = idx & 31;
    float s = 0.0f;
#pragma unroll
    for (int k4 = 0; k4 < DD; k4 += 4) {
        float4 a = *(const float4*)(A + r * DD + k4);
        s += a.x * Bs[k4][c] + a.y * Bs[k4 + 1][c]
           + a.z * Bs[k4 + 2][c] + a.w * Bs[k4 + 3][c];
    }
    C[r * DC + c] = s;
}

// ======== L1: zero + (M3 = W4 @ fcW) ========
__global__ void k_zero(const float* __restrict__ W4, const float* __restrict__ fcW) {
    if (blockIdx.x < ZB) {
        int i = blockIdx.x * blockDim.x + threadIdx.x;
        if (i < NN) g_indeg[i] = 0;
        if (i < NG * DC) g_pool[i] = 0.0f;
        if (i < NG * 3) g_usum[i] = 0.0f;
        if (i == 0) g_poolDone = 0;
    } else {
        mm_tile(W4, fcW, g_M3, blockIdx.x - ZB);
    }
}

// ======== L2: count (+rank) + (M2 = W3 @ M3) ========
__global__ void k_count(const int* __restrict__ ei, const float* __restrict__ W3) {
    if (blockIdx.x < CB) {
        int e = blockIdx.x * blockDim.x + threadIdx.x;
        if (e >= NE) return;
        g_rank[e] = atomicAdd(&g_indeg[ei[NE + e]], 1);
    } else {
        mm_tile(W3, g_M3, g_M2, blockIdx.x - CB);
    }
}

// ======== L3: per-block inclusive scan + (M1 = W2 @ M2) ========
__global__ void k_scan1(const float* __restrict__ W2) {
    if (blockIdx.x < SCAN_NB) {
        __shared__ int s[SCAN_BS];
        int i = blockIdx.x * SCAN_BS + threadIdx.x;
        int v = (i < NN) ? g_indeg[i] : 0;
        s[threadIdx.x] = v;
        __syncthreads();
#pragma unroll
        for (int off = 1; off < SCAN_BS; off <<= 1) {
            int t = (threadIdx.x >= off) ? s[threadIdx.x - off] : 0;
            __syncthreads();
            s[threadIdx.x] += t;
            __syncthreads();
        }
        if (i < NN) g_scan_tmp[i] = s[threadIdx.x];
        if (threadIdx.x == SCAN_BS - 1) g_bsum[blockIdx.x] = s[threadIdx.x];
    } else {
        mm_tile(W2, g_M2, g_M1, blockIdx.x - SCAN_NB);
    }
}

// ======== L4: rowptr + dinv + (Wc = W1 @ M1) ========
__global__ void k_scan3(const float* __restrict__ W1) {
    if (blockIdx.x < SCAN_NB) {
        __shared__ int sred[SCAN_BS];
        int partial = 0;
        for (int j = threadIdx.x; j < blockIdx.x; j += SCAN_BS) partial += g_bsum[j];
        sred[threadIdx.x] = partial;
        __syncthreads();
#pragma unroll
        for (int off = SCAN_BS / 2; off > 0; off >>= 1) {
            if (threadIdx.x < off) sred[threadIdx.x] += sred[threadIdx.x + off];
            __syncthreads();
        }
        int base = sred[0];
        int i = blockIdx.x * SCAN_BS + threadIdx.x;
        if (i < NN) {
            int d = g_indeg[i];
            g_rowptr[i] = base + g_scan_tmp[i] - d;
            g_dinv[i]   = rsqrtf((float)d + 1.0f);
        }
    } else {
        mm_tile(W1, g_M1, g_Wc, blockIdx.x - SCAN_NB);
    }
}

// ======== L5: gemmY (blocks [0,GYB)) + cvec (block GYB) + fill (rest) ========
__global__ __launch_bounds__(256) void k_fill_gemm(
    const float* __restrict__ X, const int* __restrict__ ei,
    const float* __restrict__ b1, const float* __restrict__ b2,
    const float* __restrict__ b3, const float* __restrict__ b4,
    const float* __restrict__ fcW)
{
    __shared__ float Ws[DD][DC];
    __shared__ float As[128][33];

    if (blockIdx.x < GYB) {
        int t  = threadIdx.x;
        int m0 = blockIdx.x * 128;
        int rb = t >> 3;                  // 0..31
        int cg = (t & 7) << 2;            // col group of 4

#pragma unroll
        for (int i = 0; i < 4; i++) {
            int lin = t + i * 256;
            int r = lin >> 3, c4 = (lin & 7) << 2;
            *(float4*)&Ws[r][c4] = *(const float4*)(g_Wc + r * DC + c4);
        }

        float4 ac[4];
#pragma unroll
        for (int j = 0; j < 4; j++) ac[j] = make_float4(0.f, 0.f, 0.f, 0.f);

        for (int k0 = 0; k0 < DD; k0 += 32) {
            __syncthreads();
#pragma unroll
            for (int i = 0; i < 4; i++) {
                int lin = t + i * 256;
                int r = lin >> 3, c4 = (lin & 7) << 2;
                int gr = m0 + r;
                float4 v = make_float4(0.f, 0.f, 0.f, 0.f);
                if (gr < NN) v = *(const float4*)(X + (size_t)gr * DD + k0 + c4);
                As[r][c4 + 0] = v.x; As[r][c4 + 1] = v.y;
                As[r][c4 + 2] = v.z; As[r][c4 + 3] = v.w;
            }
            __syncthreads();
#pragma unroll
            for (int k = 0; k < 32; k++) {
                float4 wv = *(const float4*)&Ws[k0 + k][cg];
#pragma unroll
                for (int j = 0; j < 4; j++) {
                    float a = As[rb + 32 * j][k];
                    ac[j].x += a * wv.x; ac[j].y += a * wv.y;
                    ac[j].z += a * wv.z; ac[j].w += a * wv.w;
                }
            }
        }
#pragma unroll
        for (int j = 0; j < 4; j++) {
            int gr = m0 + rb + 32 * j;
            if (gr < NN)
                *(uint2*)(g_Yh0 + (size_t)gr * DC + cg) = pack_h4(ac[j]);
        }
    } else if (blockIdx.x == GYB) {
        int t = threadIdx.x;
        if (t < 128) {
            int i = t >> 5, c = t & 31;
            const float* b = (i == 0) ? b1 : (i == 1) ? b2 : (i == 2) ? b3 : b4;
            const float* M = (i == 0) ? g_M1 : (i == 1) ? g_M2 : (i == 2) ? g_M3 : fcW;
            float s = 0.0f;
#pragma unroll 8
            for (int k = 0; k < DD; k++) s += b[k] * M[k * DC + c];
            g_cv[i * DC + c] = s;
        }
    } else {
        int e = (blockIdx.x - GYB - 1) * blockDim.x + threadIdx.x;
        if (e >= NE) return;
        int s = ei[e];
        int d = ei[NE + e];
        int pos = g_rowptr[d] + g_rank[e];
        g_csr[pos] = make_int2(s, __float_as_int(g_dinv[s] * g_dinv[d]));
    }
}

// ======== vector aggregate (fp16): warp per node, 8 edges per LDG.128 ========
// grp = lane>>2 (0..7) handles edge e+grp; q = lane&3 covers 8 cols via uint4.
// fp32 accumulate across two float4 regs; 3-level shuffle reduction; grp 0 stores.
// Blocks [VB, VB+UB): scalar u-chain stage (fp32, unchanged).
template <int STAGE>
__global__ __launch_bounds__(256) void k_vagg() {
    const __half* __restrict__ Yin  = (STAGE == 1 || STAGE == 3) ? g_Yh0 : g_Yh1;
    __half*       __restrict__ Yout = (STAGE == 1 || STAGE == 3) ? g_Yh1 : g_Yh0;

    if (blockIdx.x < VB) {
        int gid  = blockIdx.x * blockDim.x + threadIdx.x;
        int n    = gid >> 5;
        if (n >= NN) return;
        int lane = gid & 31;
        int grp  = lane >> 2;            // 0..7 edge groups
        int cq   = (lane & 3) << 3;      // col base: 0,8,16,24

        int beg = g_rowptr[n], end = beg + g_indeg[n];
        float4 accA = make_float4(0.f, 0.f, 0.f, 0.f);
        float4 accB = make_float4(0.f, 0.f, 0.f, 0.f);

        for (int e = beg; e < end; e += 8) {
            int ee = e + grp;
            int2 cv = (ee < end) ? g_csr[ee] : make_int2(0, 0);
            float w = __int_as_float(cv.y);        // 0 for tail -> contributes 0
            uint4 raw = *(const uint4*)(Yin + (size_t)cv.x * DC + cq);
            float4 va, vb; unpack_h8(raw, va, vb);
            accA.x += w * va.x; accA.y += w * va.y;
            accA.z += w * va.z; accA.w += w * va.w;
            accB.x += w * vb.x; accB.y += w * vb.y;
            accB.z += w * vb.z; accB.w += w * vb.w;
        }
        // reduce across the 8 edge-groups (xor 4, 8, 16)
#pragma unroll
        for (int off = 4; off <= 16; off <<= 1) {
            accA.x += __shfl_xor_sync(0xffffffffu, accA.x, off);
            accA.y += __shfl_xor_sync(0xffffffffu, accA.y, off);
            accA.z += __shfl_xor_sync(0xffffffffu, accA.z, off);
            accA.w += __shfl_xor_sync(0xffffffffu, accA.w, off);
            accB.x += __shfl_xor_sync(0xffffffffu, accB.x, off);
            accB.y += __shfl_xor_sync(0xffffffffu, accB.y, off);
            accB.z += __shfl_xor_sync(0xffffffffu, accB.z, off);
            accB.w += __shfl_xor_sync(0xffffffffu, accB.w, off);
        }
        if (grp == 0) {
            float dv = g_dinv[n];
            float sn = dv * dv;
            uint4 sraw = *(const uint4*)(Yin + (size_t)n * DC + cq);
            float4 sa, sb; unpack_h8(sraw, sa, sb);
            accA.x += sn * sa.x; accA.y += sn * sa.y;
            accA.z += sn * sa.z; accA.w += sn * sa.w;
            accB.x += sn * sb.x; accB.y += sn * sb.y;
            accB.z += sn * sb.z; accB.w += sn * sb.w;
            *(uint4*)(Yout + (size_t)n * DC + cq) = pack_h8(accA, accB);
        }
    } else if (STAGE < 4) {
        int n = (blockIdx.x - VB) * blockDim.x + threadIdx.x;
        if (n >= NN) return;
        const float* uin = (STAGE == 2) ? g_u1 : (STAGE == 3) ? g_u2 : nullptr;
        float*      uout = (STAGE == 1) ? g_u1 : (STAGE == 2) ? g_u2 : g_u3;
        float dv = g_dinv[n];
        float acc = (STAGE == 1) ? dv * dv : dv * dv * uin[n];
        int beg = g_rowptr[n], end = beg + g_indeg[n];
        if (STAGE == 1) {
            for (int e = beg; e < end; e++) acc += __int_as_float(g_csr[e].y);
        } else {
            for (int e = beg; e < end; e++) {
                int2 cv = g_csr[e];
                acc += __int_as_float(cv.y) * uin[cv.x];
            }
        }
        uout[n] = acc;
    }
}

// ======== pool + upool + (last block) final, all in one launch ========
#define POOL_CHUNK 16
__global__ __launch_bounds__(256) void k_pool(const int* __restrict__ batch,
                                              const float* __restrict__ fcb,
                                              float* __restrict__ out) {
    if (blockIdx.x < PB) {
        int gid = blockIdx.x * blockDim.x + threadIdx.x;
        int w   = gid >> 5;
        int n0  = w * POOL_CHUNK;
        int l   = gid & 31;
        if (n0 < NN) {
            int cur = batch[n0];
            float acc = 0.0f;
            for (int i = 0; i < POOL_CHUNK && n0 + i < NN; i++) {
                int n = n0 + i;
                int g = batch[n];
                if (g != cur) {
                    atomicAdd(&g_pool[cur * DC + l], acc);
                    acc = 0.0f; cur = g;
                }
                acc += __half2float(g_Yh0[(size_t)n * DC + l]);  // final Z in g_Yh0
            }
            atomicAdd(&g_pool[cur * DC + l], acc);
        }
    } else {
        int t  = (blockIdx.x - PB) * blockDim.x + threadIdx.x;
        int n0 = t * POOL_CHUNK;
        if (n0 < NN) {
            int cur = batch[n0];
            float s1 = 0.f, s2 = 0.f, s3 = 0.f;
            for (int i = 0; i < POOL_CHUNK && n0 + i < NN; i++) {
                int n = n0 + i;
                int g = batch[n];
                if (g != cur) {
                    atomicAdd(&g_usum[cur * 3 + 0], s1);
                    atomicAdd(&g_usum[cur * 3 + 1], s2);
                    atomicAdd(&g_usum[cur * 3 + 2], s3);
                    s1 = s2 = s3 = 0.f; cur = g;
                }
                s1 += g_u1[n]; s2 += g_u2[n]; s3 += g_u3[n];
            }
            atomicAdd(&g_usum[cur * 3 + 0], s1);
            atomicAdd(&g_usum[cur * 3 + 1], s2);
            atomicAdd(&g_usum[cur * 3 + 2], s3);
        }
    }

    // last-block-done: the final 64x32 reduction epilogue
    __threadfence();
    __syncthreads();
    __shared__ unsigned sdone;
    if (threadIdx.x == 0) sdone = atomicAdd(&g_poolDone, 1u);
    __syncthreads();
    if (sdone == (unsigned)(PB + UPB - 1)) {
        for (int idx = threadIdx.x; idx < NG * DC; idx += 256) {
            int g = idx >> 5, c = idx & 31;
            int lo = 0, hi = NN;
            while (lo < hi) { int m = (lo + hi) >> 1; if (batch[m] < g) lo = m + 1; else hi = m; }
            int lo2 = lo, hi2 = NN;
            while (lo2 < hi2) { int m = (lo2 + hi2) >> 1; if (batch[m] <= g) lo2 = m + 1; else hi2 = m; }
            float cnt = (float)(lo2 - lo);

            float v = g_pool[g * DC + c]
                    + g_usum[g * 3 + 2] * g_cv[0 * DC + c]
                    + g_usum[g * 3 + 1] * g_cv[1 * DC + c]
                    + g_usum[g * 3 + 0] * g_cv[2 * DC + c]
                    + cnt * (g_cv[3 * DC + c] + fcb[c]);
            out[g * DC + c] = v / fmaxf(cnt, 1.0f);
        }
        __syncthreads();
        if (threadIdx.x == 0) g_poolDone = 0;   // reset for next graph replay
    }
}

extern "C" void kernel_launch(void* const* d_in, const int* in_sizes, int n_in,
                              void* d_out, int out_size) {
    const float* x     = (const float*)d_in[0];
    const int*   ei    = (const int*)d_in[1];
    const int*   batch = (const int*)d_in[2];
    const float* W1 = (const float*)d_in[3];
    const float* b1 = (const float*)d_in[4];
    const float* W2 = (const float*)d_in[5];
    const float* b2 = (const float*)d_in[6];
    const float* W3 = (const float*)d_in[7];
    const float* b3 = (const float*)d_in[8];
    const float* W4 = (const float*)d_in[9];
    const float* b4 = (const float*)d_in[10];
    const float* fcW = (const float*)d_in[11];
    const float* fcb = (const float*)d_in[12];
    float* out = (float*)d_out;

    const int TB = 256;
    // prep chain with the weight chain riding as extra blocks
    k_zero <<<ZB + MMB, TB>>>(W4, fcW);            // zero + M3
    k_count<<<CB + MMB, TB>>>(ei, W3);             // count/rank + M2
    k_scan1<<<SCAN_NB + MMB, TB>>>(W2);            // scan + M1
    k_scan3<<<SCAN_NB + MMB, TB>>>(W1);            // rowptr/dinv + Wc
    k_fill_gemm<<<GYB + 1 + CB, TB>>>(x, ei, b1, b2, b3, b4, fcW);  // gemmY + cvec + fill

    // Â-powers (fp16 payload, 8 edges/LDG.128) with u-chain riding along
    k_vagg<1><<<VB + UB, TB>>>();
    k_vagg<2><<<VB + UB, TB>>>();
    k_vagg<3><<<VB + UB, TB>>>();
    k_vagg<4><<<VB, TB>>>();

    // pooling + final fused (last-block-done)
    k_pool<<<PB + UPB, TB>>>(batch, fcb, out);
}

// round 17
// speedup vs baseline: 1.5570x; 1.5570x over previous
#include <cuda_runtime.h>
#include <cuda_fp16.h>
#include <cstddef>

#define NN 50000
#define NE 600000
#define DD 128
#define DC 32          // collapsed output width
#define NG 64

#define SCAN_BS 256
#define SCAN_NB ((NN + SCAN_BS - 1) / SCAN_BS)   // 196

#define VB 6250        // vector blocks per vagg (50000 warps)
#define UB SCAN_NB     // scalar-u blocks appended (196)

#define ZB  SCAN_NB                     // zero blocks
#define CB  ((NE + 255) / 256)          // count/fill blocks (2344)
#define MMB 16                          // blocks per 128x32 weight mm
#define GYB ((NN + 127) / 128)          // gemmY blocks (391)
#define PB  ((VB / 16) + 1)             // pool blocks
#define UPB ((NN / 16 + 255) / 256)     // upool blocks (13)

// -------- scratch (device globals; never passed as kernel args from host) --------
__device__ int   g_indeg[NN];
__device__ float g_dinv[NN];
__device__ int   g_rowptr[NN];
__device__ int   g_rank[NE];           // per-edge slot within dst segment
__device__ int   g_scan_tmp[NN];
__device__ int   g_bsum[SCAN_NB];
__device__ __align__(8) int2 g_csr[NE];    // (src, __float_as_int(norm)), node-ordered rows
__device__ float g_u1[NN], g_u2[NN], g_u3[NN];
__device__ __align__(16) float g_M1[DD * DC];
__device__ __align__(16) float g_M2[DD * DC];
__device__ __align__(16) float g_M3[DD * DC];
__device__ __align__(16) float g_Wc[DD * DC];
__device__ float g_cv[4 * DC];
__device__ __align__(16) __half g_Yh0[(size_t)NN * DC];   // fp16 Y ping-pong
__device__ __align__(16) __half g_Yh1[(size_t)NN * DC];
__device__ float g_pool[NG * DC];
__device__ float g_usum[NG * 3];
__device__ unsigned g_poolDone;        // zero-initialized; reset by last block

// pack/unpack helpers
__device__ __forceinline__ uint2 pack_h4(float4 a) {
    __half2 h0 = __floats2half2_rn(a.x, a.y);
    __half2 h1 = __floats2half2_rn(a.z, a.w);
    uint2 r;
    r.x = *reinterpret_cast<unsigned*>(&h0);
    r.y = *reinterpret_cast<unsigned*>(&h1);
    return r;
}
__device__ __forceinline__ float4 unpack_h4(uint2 r) {
    __half2 h0 = *reinterpret_cast<__half2*>(&r.x);
    __half2 h1 = *reinterpret_cast<__half2*>(&r.y);
    float2 f0 = __half22float2(h0);
    float2 f1 = __half22float2(h1);
    return make_float4(f0.x, f0.y, f1.x, f1.y);
}

// ======== mm tile with smem-staged B and float4 A reads ========
__device__ __forceinline__ void mm_tile(const float* __restrict__ A,
                                        const float* __restrict__ B,
                                        float* __restrict__ C, int blk) {
    __shared__ float Bs[DD][DC];     // 16 KB
    int t = threadIdx.x;
#pragma unroll
    for (int i = 0; i < 4; i++) {
        int lin = t + i * 256;       // 1024 float4 slots
        int r = lin >> 3, c4 = (lin & 7) << 2;
        *(float4*)&Bs[r][c4] = *(const float4*)(B + r * DC + c4);
    }
    __syncthreads();
    int idx = blk * 256 + t;
    int r = idx >> 5, c = idx & 31;
    float s = 0.0f;
#pragma unroll
    for (int k4 = 0; k4 < DD; k4 += 4) {
        float4 a = *(const float4*)(A + r * DD + k4);
        s += a.x * Bs[k4][c] + a.y * Bs[k4 + 1][c]
           + a.z * Bs[k4 + 2][c] + a.w * Bs[k4 + 3][c];
    }
    C[r * DC + c] = s;
}

// ======== L1: zero + (M3 = W4 @ fcW) ========
__global__ void k_zero(const float* __restrict__ W4, const float* __restrict__ fcW) {
    if (blockIdx.x < ZB) {
        int i = blockIdx.x * blockDim.x + threadIdx.x;
        if (i < NN) g_indeg[i] = 0;
        if (i < NG * DC) g_pool[i] = 0.0f;
        if (i < NG * 3) g_usum[i] = 0.0f;
        if (i == 0) g_poolDone = 0;
    } else {
        mm_tile(W4, fcW, g_M3, blockIdx.x - ZB);
    }
}

// ======== L2: count (+rank) + (M2 = W3 @ M3) ========
__global__ void k_count(const int* __restrict__ ei, const float* __restrict__ W3) {
    if (blockIdx.x < CB) {
        int e = blockIdx.x * blockDim.x + threadIdx.x;
        if (e >= NE) return;
        g_rank[e] = atomicAdd(&g_indeg[ei[NE + e]], 1);
    } else {
        mm_tile(W3, g_M3, g_M2, blockIdx.x - CB);
    }
}

// ======== L3: per-block inclusive scan + (M1 = W2 @ M2) ========
__global__ void k_scan1(const float* __restrict__ W2) {
    if (blockIdx.x < SCAN_NB) {
        __shared__ int s[SCAN_BS];
        int i = blockIdx.x * SCAN_BS + threadIdx.x;
        int v = (i < NN) ? g_indeg[i] : 0;
        s[threadIdx.x] = v;
        __syncthreads();
#pragma unroll
        for (int off = 1; off < SCAN_BS; off <<= 1) {
            int t = (threadIdx.x >= off) ? s[threadIdx.x - off] : 0;
            __syncthreads();
            s[threadIdx.x] += t;
            __syncthreads();
        }
        if (i < NN) g_scan_tmp[i] = s[threadIdx.x];
        if (threadIdx.x == SCAN_BS - 1) g_bsum[blockIdx.x] = s[threadIdx.x];
    } else {
        mm_tile(W2, g_M2, g_M1, blockIdx.x - SCAN_NB);
    }
}

// ======== L4: rowptr + dinv + (Wc = W1 @ M1) ========
__global__ void k_scan3(const float* __restrict__ W1) {
    if (blockIdx.x < SCAN_NB) {
        __shared__ int sred[SCAN_BS];
        int partial = 0;
        for (int j = threadIdx.x; j < blockIdx.x; j += SCAN_BS) partial += g_bsum[j];
        sred[threadIdx.x] = partial;
        __syncthreads();
#pragma unroll
        for (int off = SCAN_BS / 2; off > 0; off >>= 1) {
            if (threadIdx.x < off) sred[threadIdx.x] += sred[threadIdx.x + off];
            __syncthreads();
        }
        int base = sred[0];
        int i = blockIdx.x * SCAN_BS + threadIdx.x;
        if (i < NN) {
            int d = g_indeg[i];
            g_rowptr[i] = base + g_scan_tmp[i] - d;
            g_dinv[i]   = rsqrtf((float)d + 1.0f);
        }
    } else {
        mm_tile(W1, g_M1, g_Wc, blockIdx.x - SCAN_NB);
    }
}

// ======== L5: gemmY (blocks [0,GYB)) + cvec (block GYB) + fill (rest) ========
__global__ __launch_bounds__(256) void k_fill_gemm(
    const float* __restrict__ X, const int* __restrict__ ei,
    const float* __restrict__ b1, const float* __restrict__ b2,
    const float* __restrict__ b3, const float* __restrict__ b4,
    const float* __restrict__ fcW)
{
    __shared__ float Ws[DD][DC];
    __shared__ float As[128][33];

    if (blockIdx.x < GYB) {
        int t  = threadIdx.x;
        int m0 = blockIdx.x * 128;
        int rb = t >> 3;                  // 0..31
        int cg = (t & 7) << 2;            // col group of 4

#pragma unroll
        for (int i = 0; i < 4; i++) {
            int lin = t + i * 256;
            int r = lin >> 3, c4 = (lin & 7) << 2;
            *(float4*)&Ws[r][c4] = *(const float4*)(g_Wc + r * DC + c4);
        }

        float4 ac[4];
#pragma unroll
        for (int j = 0; j < 4; j++) ac[j] = make_float4(0.f, 0.f, 0.f, 0.f);

        for (int k0 = 0; k0 < DD; k0 += 32) {
            __syncthreads();
#pragma unroll
            for (int i = 0; i < 4; i++) {
                int lin = t + i * 256;
                int r = lin >> 3, c4 = (lin & 7) << 2;
                int gr = m0 + r;
                float4 v = make_float4(0.f, 0.f, 0.f, 0.f);
                if (gr < NN) v = *(const float4*)(X + (size_t)gr * DD + k0 + c4);
                As[r][c4 + 0] = v.x; As[r][c4 + 1] = v.y;
                As[r][c4 + 2] = v.z; As[r][c4 + 3] = v.w;
            }
            __syncthreads();
#pragma unroll
            for (int k = 0; k < 32; k++) {
                float4 wv = *(const float4*)&Ws[k0 + k][cg];
#pragma unroll
                for (int j = 0; j < 4; j++) {
                    float a = As[rb + 32 * j][k];
                    ac[j].x += a * wv.x; ac[j].y += a * wv.y;
                    ac[j].z += a * wv.z; ac[j].w += a * wv.w;
                }
            }
        }
#pragma unroll
        for (int j = 0; j < 4; j++) {
            int gr = m0 + rb + 32 * j;
            if (gr < NN)
                *(uint2*)(g_Yh0 + (size_t)gr * DC + cg) = pack_h4(ac[j]);
        }
    } else if (blockIdx.x == GYB) {
        int t = threadIdx.x;
        if (t < 128) {
            int i = t >> 5, c = t & 31;
            const float* b = (i == 0) ? b1 : (i == 1) ? b2 : (i == 2) ? b3 : b4;
            const float* M = (i == 0) ? g_M1 : (i == 1) ? g_M2 : (i == 2) ? g_M3 : fcW;
            float s = 0.0f;
#pragma unroll 8
            for (int k = 0; k < DD; k++) s += b[k] * M[k * DC + c];
            g_cv[i * DC + c] = s;
        }
    } else {
        int e = (blockIdx.x - GYB - 1) * blockDim.x + threadIdx.x;
        if (e >= NE) return;
        int s = ei[e];
        int d = ei[NE + e];
        int pos = g_rowptr[d] + g_rank[e];
        g_csr[pos] = make_int2(s, __float_as_int(g_dinv[s] * g_dinv[d]));
    }
}

// ======== vector aggregate (fp16, R15 layout + MLP-2): warp per node ========
// grp = lane>>3 (0..3) handles edges e+grp and e+4+grp; lane covers 4 cols (uint2).
// Two independent csr loads + two gathers issued per iteration; tails predicated
// via w=0 (csr[beg] re-read harmlessly). fp32 accumulate; fp16 store.
// Blocks [VB, VB+UB): scalar u-chain stage (fp32, unchanged).
template <int STAGE>
__global__ __launch_bounds__(256) void k_vagg() {
    const __half* __restrict__ Yin  = (STAGE == 1 || STAGE == 3) ? g_Yh0 : g_Yh1;
    __half*       __restrict__ Yout = (STAGE == 1 || STAGE == 3) ? g_Yh1 : g_Yh0;

    if (blockIdx.x < VB) {
        int gid  = blockIdx.x * blockDim.x + threadIdx.x;
        int n    = gid >> 5;
        if (n >= NN) return;
        int lane = gid & 31;
        int grp  = lane >> 3;            // 0..3
        int cg   = (lane & 7) << 2;      // col*4

        int beg = g_rowptr[n], end = beg + g_indeg[n];
        float4 acc = make_float4(0.f, 0.f, 0.f, 0.f);

        for (int e = beg; e < end; e += 8) {
            int ee0 = e + grp;
            int ee1 = e + 4 + grp;
            int2 cv0 = (ee0 < end) ? g_csr[ee0] : make_int2(0, 0);
            int2 cv1 = (ee1 < end) ? g_csr[ee1] : make_int2(0, 0);
            float w0 = __int_as_float(cv0.y);   // 0 for tail -> contributes 0
            float w1 = __int_as_float(cv1.y);
            uint2 r0 = *(const uint2*)(Yin + (size_t)cv0.x * DC + cg);
            uint2 r1 = *(const uint2*)(Yin + (size_t)cv1.x * DC + cg);
            float4 v0 = unpack_h4(r0);
            float4 v1 = unpack_h4(r1);
            acc.x += w0 * v0.x + w1 * v1.x;
            acc.y += w0 * v0.y + w1 * v1.y;
            acc.z += w0 * v0.z + w1 * v1.z;
            acc.w += w0 * v0.w + w1 * v1.w;
        }
        // reduce across the 4 edge-groups (lanes l, l+8, l+16, l+24)
#pragma unroll
        for (int off = 8; off <= 16; off <<= 1) {
            acc.x += __shfl_xor_sync(0xffffffffu, acc.x, off);
            acc.y += __shfl_xor_sync(0xffffffffu, acc.y, off);
            acc.z += __shfl_xor_sync(0xffffffffu, acc.z, off);
            acc.w += __shfl_xor_sync(0xffffffffu, acc.w, off);
        }
        if (grp == 0) {
            float dv = g_dinv[n];
            float sn = dv * dv;
            float4 self = unpack_h4(*(const uint2*)(Yin + (size_t)n * DC + cg));
            acc.x += sn * self.x; acc.y += sn * self.y;
            acc.z += sn * self.z; acc.w += sn * self.w;
            *(uint2*)(Yout + (size_t)n * DC + cg) = pack_h4(acc);
        }
    } else if (STAGE < 4) {
        int n = (blockIdx.x - VB) * blockDim.x + threadIdx.x;
        if (n >= NN) return;
        const float* uin = (STAGE == 2) ? g_u1 : (STAGE == 3) ? g_u2 : nullptr;
        float*      uout = (STAGE == 1) ? g_u1 : (STAGE == 2) ? g_u2 : g_u3;
        float dv = g_dinv[n];
        float acc = (STAGE == 1) ? dv * dv : dv * dv * uin[n];
        int beg = g_rowptr[n], end = beg + g_indeg[n];
        if (STAGE == 1) {
            for (int e = beg; e < end; e++) acc += __int_as_float(g_csr[e].y);
        } else {
            for (int e = beg; e < end; e++) {
                int2 cv = g_csr[e];
                acc += __int_as_float(cv.y) * uin[cv.x];
            }
        }
        uout[n] = acc;
    }
}

// ======== pool + upool + (last block) final, all in one launch ========
#define POOL_CHUNK 16
__global__ __launch_bounds__(256) void k_pool(const int* __restrict__ batch,
                                              const float* __restrict__ fcb,
                                              float* __restrict__ out) {
    if (blockIdx.x < PB) {
        int gid = blockIdx.x * blockDim.x + threadIdx.x;
        int w   = gid >> 5;
        int n0  = w * POOL_CHUNK;
        int l   = gid & 31;
        if (n0 < NN) {
            int cur = batch[n0];
            float acc = 0.0f;
            for (int i = 0; i < POOL_CHUNK && n0 + i < NN; i++) {
                int n = n0 + i;
                int g = batch[n];
                if (g != cur) {
                    atomicAdd(&g_pool[cur * DC + l], acc);
                    acc = 0.0f; cur = g;
                }
                acc += __half2float(g_Yh0[(size_t)n * DC + l]);  // final Z in g_Yh0
            }
            atomicAdd(&g_pool[cur * DC + l], acc);
        }
    } else {
        int t  = (blockIdx.x - PB) * blockDim.x + threadIdx.x;
        int n0 = t * POOL_CHUNK;
        if (n0 < NN) {
            int cur = batch[n0];
            float s1 = 0.f, s2 = 0.f, s3 = 0.f;
            for (int i = 0; i < POOL_CHUNK && n0 + i < NN; i++) {
                int n = n0 + i;
                int g = batch[n];
                if (g != cur) {
                    atomicAdd(&g_usum[cur * 3 + 0], s1);
                    atomicAdd(&g_usum[cur * 3 + 1], s2);
                    atomicAdd(&g_usum[cur * 3 + 2], s3);
                    s1 = s2 = s3 = 0.f; cur = g;
                }
                s1 += g_u1[n]; s2 += g_u2[n]; s3 += g_u3[n];
            }
            atomicAdd(&g_usum[cur * 3 + 0], s1);
            atomicAdd(&g_usum[cur * 3 + 1], s2);
            atomicAdd(&g_usum[cur * 3 + 2], s3);
        }
    }

    // last-block-done: the final 64x32 reduction epilogue
    __threadfence();
    __syncthreads();
    __shared__ unsigned sdone;
    if (threadIdx.x == 0) sdone = atomicAdd(&g_poolDone, 1u);
    __syncthreads();
    if (sdone == (unsigned)(PB + UPB - 1)) {
        for (int idx = threadIdx.x; idx < NG * DC; idx += 256) {
            int g = idx >> 5, c = idx & 31;
            int lo = 0, hi = NN;
            while (lo < hi) { int m = (lo + hi) >> 1; if (batch[m] < g) lo = m + 1; else hi = m; }
            int lo2 = lo, hi2 = NN;
            while (lo2 < hi2) { int m = (lo2 + hi2) >> 1; if (batch[m] <= g) lo2 = m + 1; else hi2 = m; }
            float cnt = (float)(lo2 - lo);

            float v = g_pool[g * DC + c]
                    + g_usum[g * 3 + 2] * g_cv[0 * DC + c]
                    + g_usum[g * 3 + 1] * g_cv[1 * DC + c]
                    + g_usum[g * 3 + 0] * g_cv[2 * DC + c]
                    + cnt * (g_cv[3 * DC + c] + fcb[c]);
            out[g * DC + c] = v / fmaxf(cnt, 1.0f);
        }
        __syncthreads();
        if (threadIdx.x == 0) g_poolDone = 0;   // reset for next graph replay
    }
}

extern "C" void kernel_launch(void* const* d_in, const int* in_sizes, int n_in,
                              void* d_out, int out_size) {
    const float* x     = (const float*)d_in[0];
    const int*   ei    = (const int*)d_in[1];
    const int*   batch = (const int*)d_in[2];
    const float* W1 = (const float*)d_in[3];
    const float* b1 = (const float*)d_in[4];
    const float* W2 = (const float*)d_in[5];
    const float* b2 = (const float*)d_in[6];
    const float* W3 = (const float*)d_in[7];
    const float* b3 = (const float*)d_in[8];
    const float* W4 = (const float*)d_in[9];
    const float* b4 = (const float*)d_in[10];
    const float* fcW = (const float*)d_in[11];
    const float* fcb = (const float*)d_in[12];
    float* out = (float*)d_out;

    const int TB = 256;
    // prep chain with the weight chain riding as extra blocks
    k_zero <<<ZB + MMB, TB>>>(W4, fcW);            // zero + M3
    k_count<<<CB + MMB, TB>>>(ei, W3);             // count/rank + M2
    k_scan1<<<SCAN_NB + MMB, TB>>>(W2);            // scan + M1
    k_scan3<<<SCAN_NB + MMB, TB>>>(W1);            // rowptr/dinv + Wc
    k_fill_gemm<<<GYB + 1 + CB, TB>>>(x, ei, b1, b2, b3, b4, fcW);  // gemmY + cvec + fill

    // Â-powers (fp16 payload, R15 layout + MLP-2) with u-chain riding along
    k_vagg<1><<<VB + UB, TB>>>();
    k_vagg<2><<<VB + UB, TB>>>();
    k_vagg<3><<<VB + UB, TB>>>();
    k_vagg<4><<<VB, TB>>>();

    // pooling + final fused (last-block-done)
    k_pool<<<PB + UPB, TB>>>(batch, fcb, out);
}